// round 16
// baseline (speedup 1.0000x reference)
#include <cuda_runtime.h>
#include <cuda_fp8.h>
#include <cstdint>

// Problem constants
#define VOCAB   50000
#define DDIM    128
#define CCH     128
#define NCLS    200
#define NSEQ    4096
#define SLEN    128
#define NVID    256
#define NSLOT   12

// fp8 scaling: x*256, w*64 -> product scale 16384
#define XSCALE  256.0f
#define WSCALE  64.0f
#define INVS    (1.0f / 16384.0f)

// Persistent-CTA smem layout (pitch 128 + XOR swizzle everywhere)
#define W_BYTES  (NSLOT * 128 * 128)        // 196608 : all 12 slots resident
#define XBUF     (132 * 128)                // 16896  : 128 rows + 4 zero-pad rows
#define OFF_W    0
#define OFF_X    (W_BYTES)                  // two X buffers
#define OFF_RED  (OFF_X + 2 * XBUF)         // 230400 : 4*128 floats
#define SMEM_TOTAL (OFF_RED + 2048)         // 232448 = 227KB opt-in max

// Scratch in device globals (no allocations allowed)
__device__ uint8_t g_e8[(size_t)VOCAB * DDIM];     // fp8 e4m3, x*256
__device__ uint8_t g_w8[NSLOT * DDIM * CCH];       // fp8 e4m3, w*64, [slot][c][d]
__device__ float   g_part[(size_t)NSEQ * 3 * CCH]; // per-seq channel maxes (raw scale)
__device__ int     g_ctr;                          // work-stealing counter

// ---------------------------------------------------------------------------
// Conversion / init kernels
// ---------------------------------------------------------------------------
__global__ void cvt_emb8_kernel(const float* __restrict__ emb) {
    int64_t i = (int64_t)blockIdx.x * blockDim.x + threadIdx.x;
    int64_t n = (int64_t)VOCAB * DDIM;
    if (i < n)
        g_e8[i] = (uint8_t)__nv_cvt_float_to_fp8(emb[i] * XSCALE, __NV_SATFINITE, __NV_E4M3);
}

// W[slot][d][c] -> g_w8[slot][c][d]
__global__ void cvt_w8_kernel(const float* __restrict__ W3,
                              const float* __restrict__ W4,
                              const float* __restrict__ W5) {
    int i = blockIdx.x * blockDim.x + threadIdx.x;          // < 196608
    if (i >= NSLOT * DDIM * CCH) return;
    int slot = i >> 14;
    int r    = i & 16383;
    int c    = r >> 7;
    int d    = r & 127;
    float v;
    if (slot < 3)      v = W3[(slot)     * 16384 + d * CCH + c];
    else if (slot < 7) v = W4[(slot - 3) * 16384 + d * CCH + c];
    else               v = W5[(slot - 7) * 16384 + d * CCH + c];
    g_w8[slot * 16384 + c * 128 + d] =
        (uint8_t)__nv_cvt_float_to_fp8(v * WSCALE, __NV_SATFINITE, __NV_E4M3);
}

__global__ void zero_out_kernel(float* __restrict__ out) {
    int i = blockIdx.x * blockDim.x + threadIdx.x;
    if (i < NVID * NCLS) out[i] = 0.0f;   // scores > 0, so 0 acts as -inf
    if (i == 0) g_ctr = 0;
}

// ---------------------------------------------------------------------------
// MMA / async-copy helpers
// ---------------------------------------------------------------------------
__device__ __forceinline__ void ldsm_x4(uint32_t* r, uint32_t addr) {
    asm volatile("ldmatrix.sync.aligned.m8n8.x4.shared.b16 {%0,%1,%2,%3}, [%4];\n"
                 : "=r"(r[0]), "=r"(r[1]), "=r"(r[2]), "=r"(r[3]) : "r"(addr));
}
__device__ __forceinline__ void mma_fp8(float* c, const uint32_t* a, uint32_t b0, uint32_t b1) {
    asm volatile(
        "mma.sync.aligned.m16n8k32.row.col.f32.e4m3.e4m3.f32 "
        "{%0,%1,%2,%3}, {%4,%5,%6,%7}, {%8,%9}, {%0,%1,%2,%3};\n"
        : "+f"(c[0]), "+f"(c[1]), "+f"(c[2]), "+f"(c[3])
        : "r"(a[0]), "r"(a[1]), "r"(a[2]), "r"(a[3]), "r"(b0), "r"(b1));
}
__device__ __forceinline__ void cpasync16(uint32_t dst, const void* src) {
    asm volatile("cp.async.cg.shared.global [%0], [%1], 16;\n" :: "r"(dst), "l"(src));
}
__device__ __forceinline__ void cp_commit() {
    asm volatile("cp.async.commit_group;\n" ::: "memory");
}
template <int N>
__device__ __forceinline__ void cp_wait() {
    asm volatile("cp.async.wait_group %0;\n" :: "n"(N) : "memory");
}

// gather one sequence's embedding rows (swizzled, rows 0..127; pads stay zero)
__device__ __forceinline__ void stage_x(const int* __restrict__ input_x,
                                        int n, uint32_t dstbase) {
    const int tid = threadIdx.x;
    #pragma unroll
    for (int i = 0; i < 2; i++) {
        int idx = tid + i * 512;               // 0..1023
        int t = idx >> 3, ch = idx & 7;
        int id = __ldg(input_x + n * SLEN + t);
        cpasync16(dstbase + t * 128 + ((ch ^ (t & 7)) << 4),
                  g_e8 + (size_t)id * DDIM + ch * 16);
    }
}

// ---------------------------------------------------------------------------
// Persistent conv kernel: grid 148, 512 threads, 1 CTA/SM.
// All 12 weight slots resident in smem; X double-buffered across sequences.
// 16 warps = 4 wm (32 tokens) x 4 wn (32 channels); acc 32 regs/thread.
// ---------------------------------------------------------------------------
__global__ __launch_bounds__(512, 1)
void conv_kernel(const int* __restrict__ input_x) {
    extern __shared__ char smem[];
    float* red = (float*)(smem + OFF_RED);     // [4][128]

    const int tid  = threadIdx.x;
    const int lane = tid & 31;
    const int warp = tid >> 5;
    const int wm   = warp >> 2;                // 0..3 : 32-token tile
    const int wn   = warp & 3;                 // 0..3 : 32-channel tile
    const uint32_t sb = (uint32_t)__cvta_generic_to_shared(smem);

    // ---- first work item ----
    if (tid == 0) ((int*)red)[0] = atomicAdd(&g_ctr, 1);
    __syncthreads();
    int cur = ((int*)red)[0];
    __syncthreads();

    // ---- stage ALL weight slots once (swizzled) ----
    #pragma unroll
    for (int i = 0; i < 24; i++) {
        int idx = tid + i * 512;               // 0..12287 16B chunks
        int row = idx >> 3, ch = idx & 7;      // row = slot*128 + c
        cpasync16(sb + OFF_W + row * 128 + ((ch ^ (row & 7)) << 4), g_w8 + idx * 16);
    }
    // zero-pad rows 128..131 of both X buffers (never rewritten)
    if (tid < 64) {
        int buf = tid >> 5, r = 128 + ((tid >> 3) & 3), ch = tid & 7;
        *(uint4*)(smem + OFF_X + buf * XBUF + r * 128 + ((ch ^ (r & 7)) << 4)) =
            make_uint4(0, 0, 0, 0);
    }
    // first X gather into buffer 0
    if (cur < NSEQ) stage_x(input_x, cur, sb + OFF_X);
    cp_commit();

    // ---- per-thread invariants ----
    const int aln = lane & 15;
    const int ahb = lane >> 4;
    const uint32_t aRowBase = (uint32_t)(wm * 32 + aln);
    const int brow = wn * 32 + (lane & 7) + ((lane >> 4) << 3);
    const int bhb  = (lane >> 3) & 1;
    uint32_t bcol[4];
    #pragma unroll
    for (int d = 0; d < 4; d++)
        bcol[d] = (uint32_t)(((2 * d + bhb) ^ (brow & 7)) << 4);
    const uint32_t wB = sb + OFF_W + brow * 128;

    int bufidx = 0;
    while (cur < NSEQ) {
        cp_wait<0>();
        __syncthreads();                       // X(cur) visible; red free
        if (tid == 0) ((int*)red)[0] = atomicAdd(&g_ctr, 1);
        __syncthreads();
        const int nxt = ((int*)red)[0];
        __syncthreads();                       // all read nxt before red reused
        if (nxt < NSEQ) stage_x(input_x, nxt, sb + OFF_X + (bufidx ^ 1) * XBUF);
        cp_commit();

        const uint32_t xb = sb + OFF_X + bufidx * XBUF;
        const uint32_t aA = xb + aRowBase * 128;

        int slot = 0;
        #pragma unroll 1
        for (int conv = 0; conv < 3; conv++) {
            const int ksz = conv + 3;
            float acc[2][4][4];
            #pragma unroll
            for (int mf = 0; mf < 2; mf++)
                #pragma unroll
                for (int o = 0; o < 4; o++)
                    #pragma unroll
                    for (int q = 0; q < 4; q++) acc[mf][o][q] = 0.0f;

            #pragma unroll 1
            for (int j = 0; j < ksz; j++, slot++) {
                const uint32_t bw  = wB + slot * 16384;
                const uint32_t s7a = (uint32_t)((aln + j) & 7);
                const uint32_t aj  = aA + (uint32_t)j * 128;
                #pragma unroll
                for (int dck = 0; dck < 4; dck++) {
                    const uint32_t acol = (uint32_t)(((2 * dck + ahb) ^ s7a) << 4);
                    uint32_t a0[4], a1[4];
                    ldsm_x4(a0, aj + acol);
                    ldsm_x4(a1, aj + 2048 + acol);
                    #pragma unroll
                    for (int ng = 0; ng < 2; ng++) {
                        uint32_t b[4];
                        ldsm_x4(b, bw + ng * 2048 + bcol[dck]);
                        mma_fp8(acc[0][ng * 2 + 0], a0, b[0], b[1]);
                        mma_fp8(acc[1][ng * 2 + 0], a1, b[0], b[1]);
                        mma_fp8(acc[0][ng * 2 + 1], a0, b[2], b[3]);
                        mma_fp8(acc[1][ng * 2 + 1], a1, b[2], b[3]);
                    }
                }
            }

            // ---- maxpool over valid window starts t <= SLEN - ksz ----
            const int tmax = SLEN - ksz;
            const float NEG = -1e30f;
            float lmax[4][2];
            #pragma unroll
            for (int o = 0; o < 4; o++) {
                float m0 = NEG, m1 = NEG;
                #pragma unroll
                for (int mf = 0; mf < 2; mf++) {
                    int tg = wm * 32 + mf * 16 + (lane >> 2);
                    bool v0 = (tg <= tmax);
                    bool v1 = (tg + 8 <= tmax);
                    m0 = fmaxf(m0, v0 ? acc[mf][o][0] : NEG);
                    m1 = fmaxf(m1, v0 ? acc[mf][o][1] : NEG);
                    m0 = fmaxf(m0, v1 ? acc[mf][o][2] : NEG);
                    m1 = fmaxf(m1, v1 ? acc[mf][o][3] : NEG);
                }
                lmax[o][0] = m0; lmax[o][1] = m1;
            }
            #pragma unroll
            for (int o = 0; o < 4; o++)
                #pragma unroll
                for (int p = 0; p < 2; p++) {
                    float v = lmax[o][p];
                    v = fmaxf(v, __shfl_xor_sync(0xffffffffu, v, 4));
                    v = fmaxf(v, __shfl_xor_sync(0xffffffffu, v, 8));
                    v = fmaxf(v, __shfl_xor_sync(0xffffffffu, v, 16));
                    lmax[o][p] = v;
                }
            if ((lane >> 2) == 0) {
                #pragma unroll
                for (int o = 0; o < 4; o++)
                    #pragma unroll
                    for (int p = 0; p < 2; p++)
                        red[wm * 128 + wn * 32 + o * 8 + (lane & 3) * 2 + p] = lmax[o][p];
            }
            __syncthreads();
            if (tid < CCH)
                g_part[(size_t)cur * 384 + conv * 128 + tid] =
                    fmaxf(fmaxf(red[tid], red[128 + tid]),
                          fmaxf(red[256 + tid], red[384 + tid]));
            __syncthreads();                   // red free for next conv
        }

        cur = nxt;
        bufidx ^= 1;
    }
}

// ---------------------------------------------------------------------------
// Epilogue kernel (register-blocked, from round 10): 128 blocks x 256 thr.
// ---------------------------------------------------------------------------
#define EP_SEQ  32
#define FPITCH  388
__global__ __launch_bounds__(256)
void epilogue_kernel(const int* __restrict__ seg_ids,
                     const float* __restrict__ b3,
                     const float* __restrict__ b4,
                     const float* __restrict__ b5,
                     const float* __restrict__ Wout,
                     const float* __restrict__ bout,
                     float* __restrict__ out) {
    extern __shared__ float feat[];            // [EP_SEQ][FPITCH]
    const int tid  = threadIdx.x;
    const int seq0 = blockIdx.x * EP_SEQ;

    for (int i = tid; i < EP_SEQ * 384; i += 256) {
        int s = i / 384, k = i - s * 384;
        int conv = k >> 7, c = k & 127;
        float v = g_part[(size_t)(seq0 + s) * 384 + k];
        float bias = (conv == 0) ? b3[c] : ((conv == 1) ? b4[c] : b5[c]);
        feat[s * FPITCH + k] = v * INVS + bias;
    }
    __syncthreads();

    if (tid < 200) {
        const int cg = tid >> 3;
        const int sg = tid & 7;
        const int c0 = cg * 8;
        const int s0 = sg * 4;

        float acc[4][8];
        #pragma unroll
        for (int j = 0; j < 8; j++) {
            float bj = bout[c0 + j];
            #pragma unroll
            for (int i = 0; i < 4; i++) acc[i][j] = bj;
        }

        const float* f0 = feat + s0 * FPITCH;
        #pragma unroll 4
        for (int k = 0; k < 384; k++) {
            const float4 w0 = *(const float4*)(Wout + k * NCLS + c0);
            const float4 w1 = *(const float4*)(Wout + k * NCLS + c0 + 4);
            float f[4];
            #pragma unroll
            for (int i = 0; i < 4; i++) f[i] = f0[i * FPITCH + k];
            #pragma unroll
            for (int i = 0; i < 4; i++) {
                acc[i][0] = fmaf(f[i], w0.x, acc[i][0]);
                acc[i][1] = fmaf(f[i], w0.y, acc[i][1]);
                acc[i][2] = fmaf(f[i], w0.z, acc[i][2]);
                acc[i][3] = fmaf(f[i], w0.w, acc[i][3]);
                acc[i][4] = fmaf(f[i], w1.x, acc[i][4]);
                acc[i][5] = fmaf(f[i], w1.y, acc[i][5]);
                acc[i][6] = fmaf(f[i], w1.z, acc[i][6]);
                acc[i][7] = fmaf(f[i], w1.w, acc[i][7]);
            }
        }

        #pragma unroll
        for (int i = 0; i < 4; i++) {
            int seg = seg_ids[seq0 + s0 + i];
            #pragma unroll
            for (int j = 0; j < 8; j++) {
                float sgm = 1.0f / (1.0f + expf(-acc[i][j]));
                atomicMax((int*)&out[seg * NCLS + c0 + j], __float_as_int(sgm)); // sgm > 0
            }
        }
    }
}

// ---------------------------------------------------------------------------
// Launch
// ---------------------------------------------------------------------------
extern "C" void kernel_launch(void* const* d_in, const int* in_sizes, int n_in,
                              void* d_out, int out_size) {
    const int*   input_x = (const int*)d_in[0];
    const int*   seg_ids = (const int*)d_in[1];
    const float* emb     = (const float*)d_in[2];
    const float* W3      = (const float*)d_in[3];
    const float* b3      = (const float*)d_in[4];
    const float* W4      = (const float*)d_in[5];
    const float* b4      = (const float*)d_in[6];
    const float* W5      = (const float*)d_in[7];
    const float* b5      = (const float*)d_in[8];
    const float* Wout    = (const float*)d_in[9];
    const float* bout    = (const float*)d_in[10];
    float*       out     = (float*)d_out;

    cudaFuncSetAttribute(conv_kernel, cudaFuncAttributeMaxDynamicSharedMemorySize, SMEM_TOTAL);
    const int ep_smem = EP_SEQ * FPITCH * 4;
    cudaFuncSetAttribute(epilogue_kernel, cudaFuncAttributeMaxDynamicSharedMemorySize, ep_smem);

    {
        int64_t nemb = (int64_t)VOCAB * DDIM;
        cvt_emb8_kernel<<<(int)((nemb + 255) / 256), 256>>>(emb);
    }
    cvt_w8_kernel<<<(NSLOT * DDIM * CCH + 255) / 256, 256>>>(W3, W4, W5);
    zero_out_kernel<<<(NVID * NCLS + 255) / 256, 256>>>(out);

    conv_kernel<<<148, 512, SMEM_TOTAL>>>(input_x);
    epilogue_kernel<<<NSEQ / EP_SEQ, 256, ep_smem>>>(seg_ids, b3, b4, b5, Wout, bout, out);
}

// round 17
// speedup vs baseline: 1.0315x; 1.0315x over previous
#include <cuda_runtime.h>
#include <cuda_fp8.h>
#include <cstdint>

// Problem constants
#define VOCAB   50000
#define DDIM    128
#define CCH     128
#define NCLS    200
#define NSEQ    4096
#define SLEN    128
#define NVID    256
#define NSLOT   12

// fp8 scaling: x*256, w*64 -> product scale 16384
#define XSCALE  256.0f
#define WSCALE  64.0f
#define INVS    (1.0f / 16384.0f)

// Persistent-CTA smem layout (pitch 128 + XOR swizzle everywhere)
#define W_BYTES  (NSLOT * 128 * 128)        // 196608 : all 12 slots resident
#define XBUF     (132 * 128)                // 16896  : 128 rows + 4 zero-pad rows
#define OFF_W    0
#define OFF_X    (W_BYTES)                  // two X buffers
#define OFF_RED  (OFF_X + 2 * XBUF)         // 230400 : 4*128 floats
#define SMEM_TOTAL (OFF_RED + 2048)         // 232448

// Scratch in device globals (no allocations allowed)
__device__ uint8_t g_e8[(size_t)VOCAB * DDIM];     // fp8 e4m3, x*256
__device__ uint8_t g_w8[NSLOT * DDIM * CCH];       // fp8 e4m3, w*64, [slot][c][d]
__device__ float   g_part[(size_t)NSEQ * 3 * CCH]; // per-seq channel maxes (raw scale)
__device__ int     g_ctr;                          // work-stealing counter

// ---------------------------------------------------------------------------
// Conversion / init kernels
// ---------------------------------------------------------------------------
__global__ void cvt_emb8_kernel(const float* __restrict__ emb) {
    int64_t i = (int64_t)blockIdx.x * blockDim.x + threadIdx.x;
    int64_t n = (int64_t)VOCAB * DDIM;
    if (i < n)
        g_e8[i] = (uint8_t)__nv_cvt_float_to_fp8(emb[i] * XSCALE, __NV_SATFINITE, __NV_E4M3);
}

// W[slot][d][c] -> g_w8[slot][c][d]
__global__ void cvt_w8_kernel(const float* __restrict__ W3,
                              const float* __restrict__ W4,
                              const float* __restrict__ W5) {
    int i = blockIdx.x * blockDim.x + threadIdx.x;          // < 196608
    if (i >= NSLOT * DDIM * CCH) return;
    int slot = i >> 14;
    int r    = i & 16383;
    int c    = r >> 7;
    int d    = r & 127;
    float v;
    if (slot < 3)      v = W3[(slot)     * 16384 + d * CCH + c];
    else if (slot < 7) v = W4[(slot - 3) * 16384 + d * CCH + c];
    else               v = W5[(slot - 7) * 16384 + d * CCH + c];
    g_w8[slot * 16384 + c * 128 + d] =
        (uint8_t)__nv_cvt_float_to_fp8(v * WSCALE, __NV_SATFINITE, __NV_E4M3);
}

__global__ void zero_out_kernel(float* __restrict__ out) {
    int i = blockIdx.x * blockDim.x + threadIdx.x;
    if (i < NVID * NCLS) out[i] = 0.0f;   // scores > 0, so 0 acts as -inf
    if (i == 0) g_ctr = 0;
}

// ---------------------------------------------------------------------------
// MMA / async-copy helpers
// ---------------------------------------------------------------------------
__device__ __forceinline__ void ldsm_x4(uint32_t* r, uint32_t addr) {
    asm volatile("ldmatrix.sync.aligned.m8n8.x4.shared.b16 {%0,%1,%2,%3}, [%4];\n"
                 : "=r"(r[0]), "=r"(r[1]), "=r"(r[2]), "=r"(r[3]) : "r"(addr));
}
__device__ __forceinline__ void mma_fp8(float* c, const uint32_t* a, uint32_t b0, uint32_t b1) {
    asm volatile(
        "mma.sync.aligned.m16n8k32.row.col.f32.e4m3.e4m3.f32 "
        "{%0,%1,%2,%3}, {%4,%5,%6,%7}, {%8,%9}, {%0,%1,%2,%3};\n"
        : "+f"(c[0]), "+f"(c[1]), "+f"(c[2]), "+f"(c[3])
        : "r"(a[0]), "r"(a[1]), "r"(a[2]), "r"(a[3]), "r"(b0), "r"(b1));
}
__device__ __forceinline__ void cpasync16(uint32_t dst, const void* src) {
    asm volatile("cp.async.cg.shared.global [%0], [%1], 16;\n" :: "r"(dst), "l"(src));
}
__device__ __forceinline__ void cp_commit() {
    asm volatile("cp.async.commit_group;\n" ::: "memory");
}
template <int N>
__device__ __forceinline__ void cp_wait() {
    asm volatile("cp.async.wait_group %0;\n" :: "n"(N) : "memory");
}

// gather one sequence's embedding rows (swizzled, rows 0..127; pads stay zero)
__device__ __forceinline__ void stage_x(const int* __restrict__ input_x,
                                        int n, uint32_t dstbase) {
    const int tid = threadIdx.x;
    #pragma unroll
    for (int i = 0; i < 2; i++) {
        int idx = tid + i * 512;               // 0..1023
        int t = idx >> 3, ch = idx & 7;
        int id = __ldg(input_x + n * SLEN + t);
        cpasync16(dstbase + t * 128 + ((ch ^ (t & 7)) << 4),
                  g_e8 + (size_t)id * DDIM + ch * 16);
    }
}

// ---------------------------------------------------------------------------
// One conv (KSZ slots starting at SLOT0), software-pipelined fragments.
// ---------------------------------------------------------------------------
template<int KSZ, int SLOT0, int CONV>
__device__ __forceinline__ void do_conv(
    const uint32_t aA, const uint32_t wB, const int aln, const int ahb,
    const uint32_t* bcol, const int lane, const int wm, const int wn,
    const int tid, float* red, const int cur)
{
    float acc[2][4][4];
    #pragma unroll
    for (int mf = 0; mf < 2; mf++)
        #pragma unroll
        for (int o = 0; o < 4; o++)
            #pragma unroll
            for (int q = 0; q < 4; q++) acc[mf][o][q] = 0.0f;

#define LOAD_FR(A, B, dck)                                                 \
    {                                                                      \
        const uint32_t acol = (uint32_t)(((2 * (dck) + ahb) ^ s7a) << 4);  \
        ldsm_x4(A[0], aj + acol);                                          \
        ldsm_x4(A[1], aj + 2048 + acol);                                   \
        ldsm_x4(B[0], bw + bcol[dck]);                                     \
        ldsm_x4(B[1], bw + 2048 + bcol[dck]);                              \
    }
#define MMA_FR(A, B)                                                       \
    {                                                                      \
        mma_fp8(acc[0][0], A[0], B[0][0], B[0][1]);                        \
        mma_fp8(acc[1][0], A[1], B[0][0], B[0][1]);                        \
        mma_fp8(acc[0][1], A[0], B[0][2], B[0][3]);                        \
        mma_fp8(acc[1][1], A[1], B[0][2], B[0][3]);                        \
        mma_fp8(acc[0][2], A[0], B[1][0], B[1][1]);                        \
        mma_fp8(acc[1][2], A[1], B[1][0], B[1][1]);                        \
        mma_fp8(acc[0][3], A[0], B[1][2], B[1][3]);                        \
        mma_fp8(acc[1][3], A[1], B[1][2], B[1][3]);                        \
    }

    #pragma unroll
    for (int j = 0; j < KSZ; j++) {
        const uint32_t bw  = wB + (uint32_t)((SLOT0 + j) * 16384);
        const uint32_t s7a = (uint32_t)((aln + j) & 7);
        const uint32_t aj  = aA + (uint32_t)(j * 128);

        uint32_t A0[2][4], B0[2][4], A1[2][4], B1[2][4];
        LOAD_FR(A0, B0, 0);
        LOAD_FR(A1, B1, 1);
        MMA_FR(A0, B0);
        LOAD_FR(A0, B0, 2);
        MMA_FR(A1, B1);
        LOAD_FR(A1, B1, 3);
        MMA_FR(A0, B0);
        MMA_FR(A1, B1);
    }
#undef LOAD_FR
#undef MMA_FR

    // ---- maxpool over valid window starts t <= SLEN - KSZ ----
    const int tmax = SLEN - KSZ;
    const float NEG = -1e30f;
    float lmax[4][2];
    #pragma unroll
    for (int o = 0; o < 4; o++) {
        float m0 = NEG, m1 = NEG;
        #pragma unroll
        for (int mf = 0; mf < 2; mf++) {
            int tg = wm * 32 + mf * 16 + (lane >> 2);
            bool v0 = (tg <= tmax);
            bool v1 = (tg + 8 <= tmax);
            m0 = fmaxf(m0, v0 ? acc[mf][o][0] : NEG);
            m1 = fmaxf(m1, v0 ? acc[mf][o][1] : NEG);
            m0 = fmaxf(m0, v1 ? acc[mf][o][2] : NEG);
            m1 = fmaxf(m1, v1 ? acc[mf][o][3] : NEG);
        }
        lmax[o][0] = m0; lmax[o][1] = m1;
    }
    #pragma unroll
    for (int o = 0; o < 4; o++)
        #pragma unroll
        for (int p = 0; p < 2; p++) {
            float v = lmax[o][p];
            v = fmaxf(v, __shfl_xor_sync(0xffffffffu, v, 4));
            v = fmaxf(v, __shfl_xor_sync(0xffffffffu, v, 8));
            v = fmaxf(v, __shfl_xor_sync(0xffffffffu, v, 16));
            lmax[o][p] = v;
        }
    if ((lane >> 2) == 0) {
        #pragma unroll
        for (int o = 0; o < 4; o++)
            #pragma unroll
            for (int p = 0; p < 2; p++)
                red[wm * 128 + wn * 32 + o * 8 + (lane & 3) * 2 + p] = lmax[o][p];
    }
    __syncthreads();
    if (tid < CCH)
        g_part[(size_t)cur * 384 + CONV * 128 + tid] =
            fmaxf(fmaxf(red[tid], red[128 + tid]),
                  fmaxf(red[256 + tid], red[384 + tid]));
    __syncthreads();                           // red free for next conv
}

// ---------------------------------------------------------------------------
// Persistent conv kernel: grid 148, 512 threads, 1 CTA/SM.
// ---------------------------------------------------------------------------
__global__ __launch_bounds__(512, 1)
void conv_kernel(const int* __restrict__ input_x) {
    extern __shared__ char smem[];
    float* red = (float*)(smem + OFF_RED);     // [4][128]

    const int tid  = threadIdx.x;
    const int lane = tid & 31;
    const int warp = tid >> 5;
    const int wm   = warp >> 2;                // 0..3 : 32-token tile
    const int wn   = warp & 3;                 // 0..3 : 32-channel tile
    const uint32_t sb = (uint32_t)__cvta_generic_to_shared(smem);

    // ---- first work item ----
    if (tid == 0) ((int*)red)[0] = atomicAdd(&g_ctr, 1);
    __syncthreads();
    int cur = ((int*)red)[0];
    __syncthreads();

    // ---- stage ALL weight slots once (swizzled) ----
    #pragma unroll
    for (int i = 0; i < 24; i++) {
        int idx = tid + i * 512;               // 0..12287 16B chunks
        int row = idx >> 3, ch = idx & 7;      // row = slot*128 + c
        cpasync16(sb + OFF_W + row * 128 + ((ch ^ (row & 7)) << 4), g_w8 + idx * 16);
    }
    // zero-pad rows 128..131 of both X buffers (never rewritten)
    if (tid < 64) {
        int buf = tid >> 5, r = 128 + ((tid >> 3) & 3), ch = tid & 7;
        *(uint4*)(smem + OFF_X + buf * XBUF + r * 128 + ((ch ^ (r & 7)) << 4)) =
            make_uint4(0, 0, 0, 0);
    }
    // first X gather into buffer 0
    if (cur < NSEQ) stage_x(input_x, cur, sb + OFF_X);
    cp_commit();

    // ---- per-thread invariants ----
    const int aln = lane & 15;
    const int ahb = lane >> 4;
    const uint32_t aRowBase = (uint32_t)(wm * 32 + aln);
    const int brow = wn * 32 + (lane & 7) + ((lane >> 4) << 3);
    const int bhb  = (lane >> 3) & 1;
    uint32_t bcol[4];
    #pragma unroll
    for (int d = 0; d < 4; d++)
        bcol[d] = (uint32_t)(((2 * d + bhb) ^ (brow & 7)) << 4);
    const uint32_t wB = sb + OFF_W + brow * 128;

    int bufidx = 0;
    while (cur < NSEQ) {
        cp_wait<0>();
        __syncthreads();                       // X(cur) visible; red free
        if (tid == 0) ((int*)red)[0] = atomicAdd(&g_ctr, 1);
        __syncthreads();
        const int nxt = ((int*)red)[0];
        __syncthreads();                       // all read nxt before red reused
        if (nxt < NSEQ) stage_x(input_x, nxt, sb + OFF_X + (bufidx ^ 1) * XBUF);
        cp_commit();

        const uint32_t xb = sb + OFF_X + bufidx * XBUF;
        const uint32_t aA = xb + aRowBase * 128;

        do_conv<3, 0, 0>(aA, wB, aln, ahb, bcol, lane, wm, wn, tid, red, cur);
        do_conv<4, 3, 1>(aA, wB, aln, ahb, bcol, lane, wm, wn, tid, red, cur);
        do_conv<5, 7, 2>(aA, wB, aln, ahb, bcol, lane, wm, wn, tid, red, cur);

        cur = nxt;
        bufidx ^= 1;
    }
}

// ---------------------------------------------------------------------------
// Epilogue kernel (register-blocked): 128 blocks x 256 thr.
// ---------------------------------------------------------------------------
#define EP_SEQ  32
#define FPITCH  388
__global__ __launch_bounds__(256)
void epilogue_kernel(const int* __restrict__ seg_ids,
                     const float* __restrict__ b3,
                     const float* __restrict__ b4,
                     const float* __restrict__ b5,
                     const float* __restrict__ Wout,
                     const float* __restrict__ bout,
                     float* __restrict__ out) {
    extern __shared__ float feat[];            // [EP_SEQ][FPITCH]
    const int tid  = threadIdx.x;
    const int seq0 = blockIdx.x * EP_SEQ;

    for (int i = tid; i < EP_SEQ * 384; i += 256) {
        int s = i / 384, k = i - s * 384;
        int conv = k >> 7, c = k & 127;
        float v = g_part[(size_t)(seq0 + s) * 384 + k];
        float bias = (conv == 0) ? b3[c] : ((conv == 1) ? b4[c] : b5[c]);
        feat[s * FPITCH + k] = v * INVS + bias;
    }
    __syncthreads();

    if (tid < 200) {
        const int cg = tid >> 3;
        const int sg = tid & 7;
        const int c0 = cg * 8;
        const int s0 = sg * 4;

        float acc[4][8];
        #pragma unroll
        for (int j = 0; j < 8; j++) {
            float bj = bout[c0 + j];
            #pragma unroll
            for (int i = 0; i < 4; i++) acc[i][j] = bj;
        }

        const float* f0 = feat + s0 * FPITCH;
        #pragma unroll 4
        for (int k = 0; k < 384; k++) {
            const float4 w0 = *(const float4*)(Wout + k * NCLS + c0);
            const float4 w1 = *(const float4*)(Wout + k * NCLS + c0 + 4);
            float f[4];
            #pragma unroll
            for (int i = 0; i < 4; i++) f[i] = f0[i * FPITCH + k];
            #pragma unroll
            for (int i = 0; i < 4; i++) {
                acc[i][0] = fmaf(f[i], w0.x, acc[i][0]);
                acc[i][1] = fmaf(f[i], w0.y, acc[i][1]);
                acc[i][2] = fmaf(f[i], w0.z, acc[i][2]);
                acc[i][3] = fmaf(f[i], w0.w, acc[i][3]);
                acc[i][4] = fmaf(f[i], w1.x, acc[i][4]);
                acc[i][5] = fmaf(f[i], w1.y, acc[i][5]);
                acc[i][6] = fmaf(f[i], w1.z, acc[i][6]);
                acc[i][7] = fmaf(f[i], w1.w, acc[i][7]);
            }
        }

        #pragma unroll
        for (int i = 0; i < 4; i++) {
            int seg = seg_ids[seq0 + s0 + i];
            #pragma unroll
            for (int j = 0; j < 8; j++) {
                float sgm = 1.0f / (1.0f + expf(-acc[i][j]));
                atomicMax((int*)&out[seg * NCLS + c0 + j], __float_as_int(sgm)); // sgm > 0
            }
        }
    }
}

// ---------------------------------------------------------------------------
// Launch
// ---------------------------------------------------------------------------
extern "C" void kernel_launch(void* const* d_in, const int* in_sizes, int n_in,
                              void* d_out, int out_size) {
    const int*   input_x = (const int*)d_in[0];
    const int*   seg_ids = (const int*)d_in[1];
    const float* emb     = (const float*)d_in[2];
    const float* W3      = (const float*)d_in[3];
    const float* b3      = (const float*)d_in[4];
    const float* W4      = (const float*)d_in[5];
    const float* b4      = (const float*)d_in[6];
    const float* W5      = (const float*)d_in[7];
    const float* b5      = (const float*)d_in[8];
    const float* Wout    = (const float*)d_in[9];
    const float* bout    = (const float*)d_in[10];
    float*       out     = (float*)d_out;

    cudaFuncSetAttribute(conv_kernel, cudaFuncAttributeMaxDynamicSharedMemorySize, SMEM_TOTAL);
    const int ep_smem = EP_SEQ * FPITCH * 4;
    cudaFuncSetAttribute(epilogue_kernel, cudaFuncAttributeMaxDynamicSharedMemorySize, ep_smem);

    {
        int64_t nemb = (int64_t)VOCAB * DDIM;
        cvt_emb8_kernel<<<(int)((nemb + 255) / 256), 256>>>(emb);
    }
    cvt_w8_kernel<<<(NSLOT * DDIM * CCH + 255) / 256, 256>>>(W3, W4, W5);
    zero_out_kernel<<<(NVID * NCLS + 255) / 256, 256>>>(out);

    conv_kernel<<<148, 512, SMEM_TOTAL>>>(input_x);
    epilogue_kernel<<<NSEQ / EP_SEQ, 256, ep_smem>>>(seg_ids, b3, b4, b5, Wout, bout, out);
}